// round 2
// baseline (speedup 1.0000x reference)
#include <cuda_runtime.h>
#include <math.h>

#define B_     256
#define NG_    64
#define HEADS  6
#define CH     192
#define NTOK   216
#define HD     32
#define M_POS  1331
#define PDIM   12
#define MROWS  (B_*NTOK)   // 55296

// ---------------- scratch (static device globals: no runtime allocation) ----------------
__device__ float g_q  [(size_t)B_*NTOK*CH];      // Q  (B,N,C)
__device__ float g_kv [(size_t)B_*NTOK*2*CH];    // [K|V] (B,N,2C)
__device__ float g_att[(size_t)B_*NTOK*CH];      // attention output (B,N,C)
__device__ float g_pos[HEADS*M_POS];             // pos table, head-major

// ---------------- tiny dynamic position-bias MLP ----------------
__device__ __forceinline__ void ln12(float* t, const float* g, const float* b) {
    float mu = 0.f;
    #pragma unroll
    for (int i = 0; i < PDIM; i++) mu += t[i];
    mu *= (1.f/PDIM);
    float v = 0.f;
    #pragma unroll
    for (int i = 0; i < PDIM; i++) { float d = t[i]-mu; v += d*d; }
    v *= (1.f/PDIM);
    float inv = rsqrtf(v + 1e-5f);
    #pragma unroll
    for (int i = 0; i < PDIM; i++) t[i] = (t[i]-mu)*inv*g[i] + b[i];
}

__global__ void pos_mlp_kernel(
    const float* __restrict__ ppw, const float* __restrict__ ppb,
    const float* __restrict__ g1,  const float* __restrict__ be1,
    const float* __restrict__ w1,  const float* __restrict__ b1,
    const float* __restrict__ g2,  const float* __restrict__ be2,
    const float* __restrict__ w2,  const float* __restrict__ b2,
    const float* __restrict__ g3,  const float* __restrict__ be3,
    const float* __restrict__ w3,  const float* __restrict__ b3)
{
    int m = blockIdx.x*blockDim.x + threadIdx.x;
    if (m >= M_POS) return;
    float c0 = (float)(m/121 - 5);
    float c1 = (float)((m/11)%11 - 5);
    float c2 = (float)(m%11 - 5);
    float t[PDIM], u[PDIM];
    #pragma unroll
    for (int i = 0; i < PDIM; i++)
        t[i] = ppw[i*3+0]*c0 + ppw[i*3+1]*c1 + ppw[i*3+2]*c2 + ppb[i];
    ln12(t, g1, be1);
    #pragma unroll
    for (int i = 0; i < PDIM; i++) {
        float acc = b1[i];
        #pragma unroll
        for (int j = 0; j < PDIM; j++) acc += w1[i*PDIM+j]*fmaxf(t[j],0.f);
        u[i] = acc;
    }
    ln12(u, g2, be2);
    #pragma unroll
    for (int i = 0; i < PDIM; i++) {
        float acc = b2[i];
        #pragma unroll
        for (int j = 0; j < PDIM; j++) acc += w2[i*PDIM+j]*fmaxf(u[j],0.f);
        t[i] = acc;
    }
    ln12(t, g3, be3);
    #pragma unroll
    for (int h = 0; h < HEADS; h++) {
        float acc = b3[h];
        #pragma unroll
        for (int j = 0; j < PDIM; j++) acc += w3[h*PDIM+j]*fmaxf(t[j],0.f);
        g_pos[h*M_POS + m] = acc;
    }
}

// ---------------- generic tiled SGEMM: C[m][n] = sum_k A[m][k]*W[n][k] + bias[n] ----------------
__global__ __launch_bounds__(256)
void gemm_bias_kernel(const float* __restrict__ A, const float* __restrict__ W,
                      const float* __restrict__ bias, float* __restrict__ Cout,
                      int Mdim, int Ndim, int Kdim)
{
    __shared__ float As[16][65];
    __shared__ float Ws[16][65];
    int tid = threadIdx.x;
    int tx = tid & 15, ty = tid >> 4;
    int m0 = blockIdx.y * 64, n0 = blockIdx.x * 64;
    float acc[4][4] = {};
    for (int k0 = 0; k0 < Kdim; k0 += 16) {
        #pragma unroll
        for (int r = 0; r < 4; r++) {
            int e = tid + 256*r;
            int k = e & 15, mm = e >> 4;
            As[k][mm] = A[(size_t)(m0+mm)*Kdim + k0 + k];
            Ws[k][mm] = W[(size_t)(n0+mm)*Kdim + k0 + k];
        }
        __syncthreads();
        #pragma unroll
        for (int k = 0; k < 16; k++) {
            float a[4], w[4];
            #pragma unroll
            for (int i = 0; i < 4; i++) a[i] = As[k][ty + 16*i];
            #pragma unroll
            for (int j = 0; j < 4; j++) w[j] = Ws[k][tx + 16*j];
            #pragma unroll
            for (int i = 0; i < 4; i++)
                #pragma unroll
                for (int j = 0; j < 4; j++)
                    acc[i][j] += a[i]*w[j];
        }
        __syncthreads();
    }
    #pragma unroll
    for (int i = 0; i < 4; i++) {
        int mm = m0 + ty + 16*i;
        #pragma unroll
        for (int j = 0; j < 4; j++) {
            int nn = n0 + tx + 16*j;
            Cout[(size_t)mm*Ndim + nn] = acc[i][j] + bias[nn];
        }
    }
}

// ---------------- fused attention: scores + pos bias + mask + softmax + PV ----------------
// one block per (b, h); K^T, V, pos slice in dynamic SMEM; 8 warps, 1 row per warp per iter.
__global__ __launch_bounds__(256)
void attn_kernel(const float* __restrict__ mask)
{
    extern __shared__ float sm[];
    float* Kt   = sm;                     // [32][216]   Kt[d*216+m]
    float* Vs   = Kt + 32*NTOK;           // [216][32]   Vs[m*32+d]
    float* posh = Vs + NTOK*32;           // [1331]
    float* pbuf = posh + M_POS;           // [8][216]

    int bh = blockIdx.x;
    int b  = bh / HEADS, h = bh % HEADS;
    int g  = b & (NG_-1);
    int tid = threadIdx.x;
    int w = tid >> 5, lane = tid & 31;

    const float* kvb = g_kv + (size_t)b*NTOK*(2*CH);
    for (int e = tid; e < NTOK*32; e += 256) {
        int d = e & 31, m = e >> 5;
        Kt[d*NTOK + m] = kvb[(size_t)m*(2*CH) + h*32 + d];
        Vs[m*32 + d]   = kvb[(size_t)m*(2*CH) + CH + h*32 + d];
    }
    for (int e = tid; e < M_POS; e += 256) posh[e] = g_pos[h*M_POS + e];
    __syncthreads();

    const float* maskb = mask + (size_t)g*NTOK*NTOK;
    const float scale = 0.17677669529663687f;   // 32^-0.5
    float* prow = pbuf + w*NTOK;

    for (int n = w; n < NTOK; n += 8) {
        float qv = g_q[((size_t)b*NTOK + n)*CH + h*32 + lane];
        int ni = n/36, nj = (n/6)%6, nk = n%6;
        float s[7];
        #pragma unroll
        for (int j = 0; j < 7; j++) s[j] = 0.f;
        #pragma unroll
        for (int d = 0; d < 32; d++) {
            float qd = __shfl_sync(0xffffffffu, qv, d);
            const float* Kd = Kt + d*NTOK;
            #pragma unroll
            for (int j = 0; j < 7; j++)
                s[j] += qd * Kd[lane + 32*j];   // j=6,m>=216 reads in-bounds SMEM garbage, discarded
        }
        float lmax = -1e30f;
        #pragma unroll
        for (int j = 0; j < 7; j++) {
            int m = lane + 32*j;
            if (m < NTOK) {
                int mi = m/36, mj = (m/6)%6, mk = m%6;
                int idx = (ni-mi+5)*121 + (nj-mj+5)*11 + (nk-mk+5);
                s[j] = s[j]*scale + posh[idx] + maskb[(size_t)n*NTOK + m];
                lmax = fmaxf(lmax, s[j]);
            }
        }
        #pragma unroll
        for (int o = 16; o > 0; o >>= 1)
            lmax = fmaxf(lmax, __shfl_xor_sync(0xffffffffu, lmax, o));
        float lsum = 0.f;
        #pragma unroll
        for (int j = 0; j < 7; j++) {
            int m = lane + 32*j;
            if (m < NTOK) {
                float e = __expf(s[j] - lmax);
                prow[m] = e;
                lsum += e;
            }
        }
        #pragma unroll
        for (int o = 16; o > 0; o >>= 1)
            lsum += __shfl_xor_sync(0xffffffffu, lsum, o);
        float inv = 1.f / lsum;
        __syncwarp();
        float acc = 0.f;
        #pragma unroll 4
        for (int m = 0; m < NTOK; m++)
            acc += prow[m] * Vs[m*32 + lane];
        g_att[((size_t)b*NTOK + n)*CH + h*32 + lane] = acc * inv;
        __syncwarp();
    }
}

// ---------------- launch ----------------
extern "C" void kernel_launch(void* const* d_in, const int* in_sizes, int n_in,
                              void* d_out, int out_size)
{
    const float* x     = (const float*)d_in[0];
    const float* y     = (const float*)d_in[1];
    const float* mask  = (const float*)d_in[2];
    const float* Wqkv  = (const float*)d_in[3];
    const float* bqkv  = (const float*)d_in[4];
    const float* Wproj = (const float*)d_in[5];
    const float* bproj = (const float*)d_in[6];
    const float* ppw   = (const float*)d_in[7];
    const float* ppb   = (const float*)d_in[8];
    const float* g1    = (const float*)d_in[9];
    const float* be1   = (const float*)d_in[10];
    const float* w1    = (const float*)d_in[11];
    const float* b1    = (const float*)d_in[12];
    const float* g2    = (const float*)d_in[13];
    const float* be2   = (const float*)d_in[14];
    const float* w2    = (const float*)d_in[15];
    const float* b2    = (const float*)d_in[16];
    const float* g3    = (const float*)d_in[17];
    const float* be3   = (const float*)d_in[18];
    const float* w3    = (const float*)d_in[19];
    const float* b3    = (const float*)d_in[20];
    float* out = (float*)d_out;

    float *qp, *kvp, *attp;
    cudaGetSymbolAddress((void**)&qp,  g_q);
    cudaGetSymbolAddress((void**)&kvp, g_kv);
    cudaGetSymbolAddress((void**)&attp, g_att);

    // 1. position-bias MLP table (heads x 1331)
    pos_mlp_kernel<<<(M_POS+255)/256, 256>>>(ppw, ppb, g1, be1, w1, b1,
                                             g2, be2, w2, b2, g3, be3, w3, b3);
    // 2. Q = x @ Wq^T + bq   (rows 0..191 of Wqkv)
    {
        dim3 grid(CH/64, MROWS/64);
        gemm_bias_kernel<<<grid, 256>>>(x, Wqkv, bqkv, qp, MROWS, CH, CH);
    }
    // 3. KV = y @ Wkv^T + bkv (rows 192..575 of Wqkv)
    {
        dim3 grid((2*CH)/64, MROWS/64);
        gemm_bias_kernel<<<grid, 256>>>(y, Wqkv + (size_t)CH*CH, bqkv + CH,
                                        kvp, MROWS, 2*CH, CH);
    }
    // 4. fused attention
    {
        size_t smem = (size_t)(32*NTOK + NTOK*32 + M_POS + 8*NTOK) * sizeof(float);
        cudaFuncSetAttribute(attn_kernel, cudaFuncAttributeMaxDynamicSharedMemorySize, (int)smem);
        attn_kernel<<<B_*HEADS, 256, smem>>>(mask);
    }
    // 5. projection
    {
        dim3 grid(CH/64, MROWS/64);
        gemm_bias_kernel<<<grid, 256>>>(attp, Wproj, bproj, out, MROWS, CH, CH);
    }
}

// round 3
// speedup vs baseline: 1.6184x; 1.6184x over previous
#include <cuda_runtime.h>
#include <math.h>

#define B_     256
#define NG_    64
#define HEADS  6
#define CH     192
#define NTOK   216
#define HD     32
#define M_POS  1331
#define PDIM   12
#define MROWS  (B_*NTOK)   // 55296

#define KSTR   225         // Kt row stride (odd: conflict-free transposed STS; >=224 for j=6 pad)
#define VSTR   220         // Vt row stride (mult of 4 for float4; phase-conflict-free)
#define POSPAD 1336        // posh padded for 16B alignment of pbuf

// ---------------- scratch ----------------
__device__ float g_q  [(size_t)B_*NTOK*CH];
__device__ float g_kv [(size_t)B_*NTOK*2*CH];
__device__ float g_att[(size_t)B_*NTOK*CH];
__device__ float g_pos[HEADS*M_POS];

// ---------------- tiny dynamic position-bias MLP ----------------
__device__ __forceinline__ void ln12(float* t, const float* g, const float* b) {
    float mu = 0.f;
    #pragma unroll
    for (int i = 0; i < PDIM; i++) mu += t[i];
    mu *= (1.f/PDIM);
    float v = 0.f;
    #pragma unroll
    for (int i = 0; i < PDIM; i++) { float d = t[i]-mu; v += d*d; }
    v *= (1.f/PDIM);
    float inv = rsqrtf(v + 1e-5f);
    #pragma unroll
    for (int i = 0; i < PDIM; i++) t[i] = (t[i]-mu)*inv*g[i] + b[i];
}

__global__ void pos_mlp_kernel(
    const float* __restrict__ ppw, const float* __restrict__ ppb,
    const float* __restrict__ g1,  const float* __restrict__ be1,
    const float* __restrict__ w1,  const float* __restrict__ b1,
    const float* __restrict__ g2,  const float* __restrict__ be2,
    const float* __restrict__ w2,  const float* __restrict__ b2,
    const float* __restrict__ g3,  const float* __restrict__ be3,
    const float* __restrict__ w3,  const float* __restrict__ b3)
{
    int m = blockIdx.x*blockDim.x + threadIdx.x;
    if (m >= M_POS) return;
    float c0 = (float)(m/121 - 5);
    float c1 = (float)((m/11)%11 - 5);
    float c2 = (float)(m%11 - 5);
    float t[PDIM], u[PDIM];
    #pragma unroll
    for (int i = 0; i < PDIM; i++)
        t[i] = ppw[i*3+0]*c0 + ppw[i*3+1]*c1 + ppw[i*3+2]*c2 + ppb[i];
    ln12(t, g1, be1);
    #pragma unroll
    for (int i = 0; i < PDIM; i++) {
        float acc = b1[i];
        #pragma unroll
        for (int j = 0; j < PDIM; j++) acc += w1[i*PDIM+j]*fmaxf(t[j],0.f);
        u[i] = acc;
    }
    ln12(u, g2, be2);
    #pragma unroll
    for (int i = 0; i < PDIM; i++) {
        float acc = b2[i];
        #pragma unroll
        for (int j = 0; j < PDIM; j++) acc += w2[i*PDIM+j]*fmaxf(u[j],0.f);
        t[i] = acc;
    }
    ln12(t, g3, be3);
    #pragma unroll
    for (int h = 0; h < HEADS; h++) {
        float acc = b3[h];
        #pragma unroll
        for (int j = 0; j < PDIM; j++) acc += w3[h*PDIM+j]*fmaxf(t[j],0.f);
        g_pos[h*M_POS + m] = acc;
    }
}

// ---------------- float4 tiled SGEMM: C[m][n] = sum_k A[m][k]*W[n][k] + bias[n] ----------------
// 64x64 tile, 256 threads, 4x4 contiguous microtile, software-pipelined global loads.
__global__ __launch_bounds__(256)
void gemm_bias_kernel(const float* __restrict__ A, const float* __restrict__ W,
                      const float* __restrict__ bias, float* __restrict__ Cout,
                      int Mdim, int Ndim, int Kdim)
{
    __shared__ float As[16][68];
    __shared__ float Ws[16][68];
    int tid = threadIdx.x;
    int tx = tid & 15, ty = tid >> 4;
    int m0 = blockIdx.y * 64, n0 = blockIdx.x * 64;
    int lrow = tid >> 2;          // 0..63
    int lk4  = (tid & 3) * 4;     // 0,4,8,12

    const float* Aptr = A + (size_t)(m0 + lrow)*Kdim + lk4;
    const float* Wptr = W + (size_t)(n0 + lrow)*Kdim + lk4;

    float4 aR = *(const float4*)Aptr;
    float4 wR = *(const float4*)Wptr;
    float acc[4][4] = {};
    int nt = Kdim >> 4;

    for (int t = 0;;) {
        As[lk4+0][lrow] = aR.x; As[lk4+1][lrow] = aR.y;
        As[lk4+2][lrow] = aR.z; As[lk4+3][lrow] = aR.w;
        Ws[lk4+0][lrow] = wR.x; Ws[lk4+1][lrow] = wR.y;
        Ws[lk4+2][lrow] = wR.z; Ws[lk4+3][lrow] = wR.w;
        __syncthreads();
        t++;
        if (t < nt) {
            aR = *(const float4*)(Aptr + t*16);
            wR = *(const float4*)(Wptr + t*16);
        }
        #pragma unroll
        for (int k = 0; k < 16; k++) {
            float4 a4 = *(const float4*)&As[k][ty*4];
            float4 w4 = *(const float4*)&Ws[k][tx*4];
            acc[0][0] += a4.x*w4.x; acc[0][1] += a4.x*w4.y; acc[0][2] += a4.x*w4.z; acc[0][3] += a4.x*w4.w;
            acc[1][0] += a4.y*w4.x; acc[1][1] += a4.y*w4.y; acc[1][2] += a4.y*w4.z; acc[1][3] += a4.y*w4.w;
            acc[2][0] += a4.z*w4.x; acc[2][1] += a4.z*w4.y; acc[2][2] += a4.z*w4.z; acc[2][3] += a4.z*w4.w;
            acc[3][0] += a4.w*w4.x; acc[3][1] += a4.w*w4.y; acc[3][2] += a4.w*w4.z; acc[3][3] += a4.w*w4.w;
        }
        if (t >= nt) break;
        __syncthreads();
    }

    float4 b4 = *(const float4*)(bias + n0 + 4*tx);
    #pragma unroll
    for (int i = 0; i < 4; i++) {
        float4 o;
        o.x = acc[i][0] + b4.x; o.y = acc[i][1] + b4.y;
        o.z = acc[i][2] + b4.z; o.w = acc[i][3] + b4.w;
        *(float4*)&Cout[(size_t)(m0 + 4*ty + i)*Ndim + n0 + 4*tx] = o;
    }
}

// ---------------- fused attention ----------------
// one block per (b,h); 8 warps; each warp processes 4 query rows per group.
__global__ __launch_bounds__(256)
void attn_kernel(const float* __restrict__ mask)
{
    extern __shared__ float sm[];
    float* Kt   = sm;                 // [32][KSTR]  Kt[d*KSTR+m]
    float* Vt   = Kt + 32*KSTR;       // [32][VSTR]  Vt[d*VSTR+m]
    float* posh = Vt + 32*VSTR;       // [POSPAD]
    float* pbuf = posh + POSPAD;      // [8][4*216]

    int bh = blockIdx.x;
    int b  = bh / HEADS, h = bh % HEADS;
    int g  = b & (NG_-1);
    int tid = threadIdx.x;
    int w = tid >> 5, lane = tid & 31;

    const float* kvb = g_kv + (size_t)b*NTOK*(2*CH);
    for (int e = tid; e < NTOK*32; e += 256) {
        int m = e >> 5, d = e & 31;
        Kt[d*KSTR + m] = kvb[(size_t)m*(2*CH) + h*32 + d];
        Vt[d*VSTR + m] = kvb[(size_t)m*(2*CH) + CH + h*32 + d];
    }
    for (int e = tid; e < 32*(KSTR-NTOK); e += 256) {   // zero Kt pad (m=216..KSTR-1)
        int d = e / (KSTR-NTOK), p = e - d*(KSTR-NTOK);
        Kt[d*KSTR + NTOK + p] = 0.f;
    }
    for (int e = tid; e < M_POS; e += 256) posh[e] = g_pos[h*M_POS + e];
    __syncthreads();

    const float* maskb = mask + (size_t)g*NTOK*NTOK;
    const float scale    = 0.17677669529663687f;  // 32^-0.5
    const float invscale = 5.656854249492381f;    // 32^0.5
    float* pw = pbuf + w*(4*NTOK);

    // per-thread precompute of target-index component for each j
    int mid[7];
    #pragma unroll
    for (int j = 0; j < 7; j++) {
        int m = lane + 32*j;
        mid[j] = (m/36)*121 + ((m/6)%6)*11 + (m%6);
    }

    for (int grp = w; grp < NTOK/4; grp += 8) {
        int n0 = grp*4;
        float qv[4];
        #pragma unroll
        for (int r = 0; r < 4; r++)
            qv[r] = g_q[((size_t)b*NTOK + n0 + r)*CH + h*32 + lane];

        // init accumulators with (pos_bias + mask)/scale (overlaps L2 latency with QK)
        float s[4][7];
        #pragma unroll
        for (int r = 0; r < 4; r++) {
            int n = n0 + r;
            int nid = (n/36)*121 + ((n/6)%6)*11 + (n%6);
            #pragma unroll
            for (int j = 0; j < 7; j++) {
                int m = lane + 32*j;
                s[r][j] = (m < NTOK)
                    ? (posh[nid - mid[j] + 665] + maskb[(size_t)n*NTOK + m]) * invscale
                    : 0.f;
            }
        }

        // QK^T: 4-row register blocking, K reused 4x
        #pragma unroll
        for (int d = 0; d < 32; d++) {
            float kreg[7];
            const float* Kd = Kt + d*KSTR + lane;
            #pragma unroll
            for (int j = 0; j < 7; j++) kreg[j] = Kd[32*j];
            #pragma unroll
            for (int r = 0; r < 4; r++) {
                float qd = __shfl_sync(0xffffffffu, qv[r], d);
                #pragma unroll
                for (int j = 0; j < 7; j++) s[r][j] += qd * kreg[j];
            }
        }

        // softmax per row
        float inv_[4];
        #pragma unroll
        for (int r = 0; r < 4; r++) {
            float lmax = -1e30f;
            #pragma unroll
            for (int j = 0; j < 7; j++) {
                float f = ((lane + 32*j) < NTOK) ? s[r][j]*scale : -1e30f;
                s[r][j] = f;
                lmax = fmaxf(lmax, f);
            }
            #pragma unroll
            for (int o = 16; o > 0; o >>= 1)
                lmax = fmaxf(lmax, __shfl_xor_sync(0xffffffffu, lmax, o));
            float lsum = 0.f;
            #pragma unroll
            for (int j = 0; j < 7; j++) {
                float e = __expf(s[r][j] - lmax);
                int m = lane + 32*j;
                if (m < NTOK) pw[r*NTOK + m] = e;
                lsum += e;
            }
            #pragma unroll
            for (int o = 16; o > 0; o >>= 1)
                lsum += __shfl_xor_sync(0xffffffffu, lsum, o);
            inv_[r] = 1.f / lsum;
        }
        __syncwarp();

        // PV: lane owns output dim d=lane; float4 dot products along m, V reused 4x
        float acc0 = 0.f, acc1 = 0.f, acc2 = 0.f, acc3 = 0.f;
        const float* vrow = Vt + lane*VSTR;
        #pragma unroll 2
        for (int mq = 0; mq < NTOK/4; mq++) {
            float4 v = *(const float4*)(vrow + 4*mq);
            float4 p0 = *(const float4*)(pw + 0*NTOK + 4*mq);
            float4 p1 = *(const float4*)(pw + 1*NTOK + 4*mq);
            float4 p2 = *(const float4*)(pw + 2*NTOK + 4*mq);
            float4 p3 = *(const float4*)(pw + 3*NTOK + 4*mq);
            acc0 += p0.x*v.x + p0.y*v.y + p0.z*v.z + p0.w*v.w;
            acc1 += p1.x*v.x + p1.y*v.y + p1.z*v.z + p1.w*v.w;
            acc2 += p2.x*v.x + p2.y*v.y + p2.z*v.z + p2.w*v.w;
            acc3 += p3.x*v.x + p3.y*v.y + p3.z*v.z + p3.w*v.w;
        }
        float accs[4] = {acc0, acc1, acc2, acc3};
        #pragma unroll
        for (int r = 0; r < 4; r++)
            g_att[((size_t)b*NTOK + n0 + r)*CH + h*32 + lane] = accs[r] * inv_[r];
        __syncwarp();
    }
}

// ---------------- launch ----------------
extern "C" void kernel_launch(void* const* d_in, const int* in_sizes, int n_in,
                              void* d_out, int out_size)
{
    const float* x     = (const float*)d_in[0];
    const float* y     = (const float*)d_in[1];
    const float* mask  = (const float*)d_in[2];
    const float* Wqkv  = (const float*)d_in[3];
    const float* bqkv  = (const float*)d_in[4];
    const float* Wproj = (const float*)d_in[5];
    const float* bproj = (const float*)d_in[6];
    const float* ppw   = (const float*)d_in[7];
    const float* ppb   = (const float*)d_in[8];
    const float* g1    = (const float*)d_in[9];
    const float* be1   = (const float*)d_in[10];
    const float* w1    = (const float*)d_in[11];
    const float* b1    = (const float*)d_in[12];
    const float* g2    = (const float*)d_in[13];
    const float* be2   = (const float*)d_in[14];
    const float* w2    = (const float*)d_in[15];
    const float* b2    = (const float*)d_in[16];
    const float* g3    = (const float*)d_in[17];
    const float* be3   = (const float*)d_in[18];
    const float* w3    = (const float*)d_in[19];
    const float* b3    = (const float*)d_in[20];
    float* out = (float*)d_out;

    float *qp, *kvp, *attp;
    cudaGetSymbolAddress((void**)&qp,  g_q);
    cudaGetSymbolAddress((void**)&kvp, g_kv);
    cudaGetSymbolAddress((void**)&attp, g_att);

    pos_mlp_kernel<<<(M_POS+255)/256, 256>>>(ppw, ppb, g1, be1, w1, b1,
                                             g2, be2, w2, b2, g3, be3, w3, b3);
    {
        dim3 grid(CH/64, MROWS/64);
        gemm_bias_kernel<<<grid, 256>>>(x, Wqkv, bqkv, qp, MROWS, CH, CH);
    }
    {
        dim3 grid((2*CH)/64, MROWS/64);
        gemm_bias_kernel<<<grid, 256>>>(y, Wqkv + (size_t)CH*CH, bqkv + CH,
                                        kvp, MROWS, 2*CH, CH);
    }
    {
        size_t smem = (size_t)(32*KSTR + 32*VSTR + POSPAD + 8*4*NTOK) * sizeof(float);
        cudaFuncSetAttribute(attn_kernel, cudaFuncAttributeMaxDynamicSharedMemorySize, (int)smem);
        attn_kernel<<<B_*HEADS, 256, smem>>>(mask);
    }
    {
        dim3 grid(CH/64, MROWS/64);
        gemm_bias_kernel<<<grid, 256>>>(attp, Wproj, bproj, out, MROWS, CH, CH);
    }
}